// round 7
// baseline (speedup 1.0000x reference)
#include <cuda_runtime.h>
#include <cuda_bf16.h>

// y[b] = sum over segments s of w[s]*f_s; f_s picks highest-m valid candidate
// (m, l=s-3m) with x[m] in (phi-iv[m], phi+iv[m]], value 0.5*cos(x[m]-phi)+0.5.
// Per row: y = C0 cos x0 + S0 sin x0 + C1 cos x1 + S1 sin x1 + C2 cos x2 + S2 sin x2 + T
// with coefficients a function of the rank triple (r0,r1,r2) of x[m] among each
// m's 32 sorted window bounds.
//   (C0,S0,T0)        = f(r0,r1,r2) -> 33^3 L2 table, 16B = 1 sector, 1 LDG.128
//   (C1,S1,C2,S2,T12) = f(r1,r2)    -> 1089-entry smem table (SoA, single folded in)
// Rank via 1024-cell uint8 LUT (+ exact forward walk).
// Output: [ y (batch floats), weight (48 floats) ].

#define TPB 256
#define RPT 4
#define NR    33
#define NPAIR (NR * NR)       // 1089
#define NTAB  (NR * NR * NR)  // 35937
#define GLUT  1024

__device__ float   gSortedB[96];       // [m*32 + pos]
__device__ float4  gTrip[NTAB];        // (C0,S0,T0,0)
__device__ float4  gPairQ[NPAIR];      // (C1,S1,C2,S2)
__device__ float   gPairT[NPAIR];      // T1 + T2
__device__ unsigned char gLUT[3][GLUT];
__device__ float2  gGrid[3];           // (lo, invw) per m

// ---------------- fused setup ----------------------------------------------
__global__ void __launch_bounds__(TPB)
setup_all(const float* __restrict__ phis,
          const float* __restrict__ interval,
          const float* __restrict__ weight) {
    __shared__ float    sv[96];
    __shared__ int      spos[96];
    __shared__ float    ssort[96];
    __shared__ float    svc[3][3][16];   // [m][{c,s,t}][l]
    __shared__ unsigned sSH[3][NR];

    const int t = threadIdx.x;

    if (t < 96) {
        const int m = t >> 5, i = t & 31, l = i & 15;
        const float p  = phis[m * 16 + l];
        const float iv = interval[m];
        sv[t] = (i < 16) ? (p - iv) : (p + iv);
    }
    if (t < 48) {
        const int m = t >> 4, l = t & 15;
        const float w = 0.5f * weight[3 * m + l];    // segment s = 3m + l
        const float p = phis[m * 16 + l];
        float sp, cp;
        sincosf(p, &sp, &cp);
        svc[m][0][l] = w * cp;
        svc[m][1][l] = w * sp;
        svc[m][2][l] = w;
    }
    __syncthreads();

    // stable rank-sort of each m's 32 bounds
    if (t < 96) {
        const int m = t >> 5, i = t & 31;
        const float v = sv[t];
        int pos = 0;
        for (int j = 0; j < 32; ++j) {
            const float u = sv[(m << 5) + j];
            pos += (u < v || (u == v && j < i)) ? 1 : 0;
        }
        spos[t] = pos;
        ssort[(m << 5) + pos] = v;
        if (blockIdx.x == 0) gSortedB[(m << 5) + pos] = v;
    }
    __syncthreads();

    // hitmask per rank r in segment space
    if (t < 3 * NR) {
        const int m = t / NR, r = t - m * NR;
        unsigned mask = 0;
        for (int l = 0; l < 16; ++l) {
            const int plo  = spos[(m << 5) + l];
            const int phi_ = spos[(m << 5) + 16 + l];
            if (plo < r && phi_ >= r) mask |= (1u << l);
        }
        sSH[m][r] = mask << (3 * m);
    }
    __syncthreads();

    if (blockIdx.x == 0) {
        // grid params + rank LUT per m
        if (t < 3) {
            const float lo = ssort[t << 5];
            const float hi = ssort[(t << 5) + 31];
            const float span = hi - lo;
            gGrid[t] = make_float2(lo, (span > 0.0f) ? ((float)GLUT / span) : 0.0f);
        }
        __syncthreads();
        for (int e = t; e < 3 * GLUT; e += TPB) {
            const int m = e / GLUT, c = e - m * GLUT;
            const float lo = ssort[m << 5];
            const float hi = ssort[(m << 5) + 31];
            const float w  = (hi - lo) / (float)GLUT;
            const float gp = lo + (float)c * w;      // cell left edge
            int r = 0;
            for (int j = 0; j < 32; ++j) r += (ssort[(m << 5) + j] < gp) ? 1 : 0;
            gLUT[m][c] = (unsigned char)r;
        }
        // pair table: W1 = H1 & ~H2 plus single (W2 = H2) folded in
        for (int e = t; e < NPAIR; e += TPB) {
            const int r1 = e / NR, r2 = e - r1 * NR;
            const unsigned h2 = sSH[2][r2];
            const unsigned W1 = sSH[1][r1] & ~h2;
            float C1 = 0.f, S1 = 0.f, C2 = 0.f, S2 = 0.f, T = 0.f;
            for (int l = 0; l < 16; ++l) {
                if (W1 & (1u << (3 + l))) { C1 += svc[1][0][l]; S1 += svc[1][1][l]; T += svc[1][2][l]; }
                if (h2 & (1u << (6 + l))) { C2 += svc[2][0][l]; S2 += svc[2][1][l]; T += svc[2][2][l]; }
            }
            gPairQ[e] = make_float4(C1, S1, C2, S2);
            gPairT[e] = T;
        }
    }

    // triple table: W0 = H0 & ~H1 & ~H2
    for (int e = blockIdx.x * TPB + t; e < NTAB; e += gridDim.x * TPB) {
        const int r0  = e / NPAIR;
        const int rem = e - r0 * NPAIR;
        const int r1  = rem / NR;
        const int r2  = rem - r1 * NR;
        const unsigned W0 = sSH[0][r0] & ~sSH[1][r1] & ~sSH[2][r2];
        float C = 0.f, S = 0.f, T = 0.f;
        for (int l = 0; l < 16; ++l)
            if (W0 & (1u << l)) { C += svc[0][0][l]; S += svc[0][1][l]; T += svc[0][2][l]; }
        gTrip[e] = make_float4(C, S, T, 0.0f);
    }
}

// ---------------- main ------------------------------------------------------
__global__ void __launch_bounds__(TPB)
glm_main(const float* __restrict__ x,
         const float* __restrict__ weight,
         float* __restrict__ out, int batch) {
    __shared__ float         sb[96];
    __shared__ float4        sPQ[NPAIR];
    __shared__ float         sPT[NPAIR];
    __shared__ unsigned char sLUT[3][GLUT];
    __shared__ float2        sGrid[3];

    const int t = threadIdx.x;
    if (t < 96) sb[t] = gSortedB[t];
    if (t < 3)  sGrid[t] = gGrid[t];
    for (int i = t; i < NPAIR; i += TPB) { sPQ[i] = gPairQ[i]; sPT[i] = gPairT[i]; }
    {   // stage LUT as 32-bit words
        const unsigned* src = reinterpret_cast<const unsigned*>(gLUT);
        unsigned* dst = reinterpret_cast<unsigned*>(sLUT);
        for (int i = t; i < 3 * GLUT / 4; i += TPB) dst[i] = src[i];
    }
    if (blockIdx.x == 0 && t < 48) out[batch + t] = weight[t];   // weight tail
    __syncthreads();

    const int tid = blockIdx.x * TPB + t;
    const long long row0 = (long long)tid * RPT;
    if (row0 >= batch) return;

    const float4* xv = reinterpret_cast<const float4*>(x + row0 * 3);
    const float4 va = xv[0], vb = xv[1], vc = xv[2];
    const float X[RPT][3] = {
        {va.x, va.y, va.z}, {va.w, vb.x, vb.y},
        {vb.z, vb.w, vc.x}, {vc.y, vc.z, vc.w}
    };

    const float2 g0 = sGrid[0], g1 = sGrid[1], g2 = sGrid[2];

    float Y[RPT];
#pragma unroll
    for (int r = 0; r < RPT; ++r) {
        const float x0 = X[r][0], x1 = X[r][1], x2 = X[r][2];

        // rank via LUT (conservative -1 cell) + exact forward walk
        int i0 = (int)((x0 - g0.x) * g0.y) - 1;  i0 = min(max(i0, 0), GLUT - 1);
        int i1 = (int)((x1 - g1.x) * g1.y) - 1;  i1 = min(max(i1, 0), GLUT - 1);
        int i2 = (int)((x2 - g2.x) * g2.y) - 1;  i2 = min(max(i2, 0), GLUT - 1);
        int ra = sLUT[0][i0];
        int rb = sLUT[1][i1];
        int rc = sLUT[2][i2];
        while (ra < 32 && sb[ra]      < x0) ++ra;
        while (rb < 32 && sb[32 + rb] < x1) ++rb;
        while (rc < 32 && sb[64 + rc] < x2) ++rc;

        const int e12 = rb * NR + rc;
        const float4 tv = __ldg(&gTrip[(ra * NR + rb) * NR + rc]);  // 1 sector
        const float4 pq = sPQ[e12];
        const float  pt = sPT[e12];

        float s0, c0, s1, c1, s2, c2;
        __sincosf(x0, &s0, &c0);
        __sincosf(x1, &s1, &c1);
        __sincosf(x2, &s2, &c2);

        float y = tv.z + pt;
        y = fmaf(c0, tv.x, y); y = fmaf(s0, tv.y, y);
        y = fmaf(c1, pq.x, y); y = fmaf(s1, pq.y, y);
        y = fmaf(c2, pq.z, y); y = fmaf(s2, pq.w, y);
        Y[r] = y;
    }

    reinterpret_cast<float4*>(out)[tid] = make_float4(Y[0], Y[1], Y[2], Y[3]);
}

extern "C" void kernel_launch(void* const* d_in, const int* in_sizes, int n_in,
                              void* d_out, int out_size) {
    const float* x        = (const float*)d_in[0];
    const float* phis     = (const float*)d_in[1];
    const float* interval = (const float*)d_in[2];
    const float* weight   = (const float*)d_in[3];
    float* out = (float*)d_out;

    const int batch = in_sizes[0] / 3;
    const int n_threads = (batch + RPT - 1) / RPT;
    const int n_blocks  = (n_threads + TPB - 1) / TPB;

    setup_all<<<(NTAB + TPB - 1) / TPB, TPB>>>(phis, interval, weight);
    glm_main<<<n_blocks, TPB>>>(x, weight, out, batch);
}

// round 8
// speedup vs baseline: 1.3532x; 1.3532x over previous
#include <cuda_runtime.h>
#include <cuda_bf16.h>

// y[b] = sum over segments s of w[s]*f_s; f_s picks highest-m valid candidate
// (m, l=s-3m) with x[m] in (phi-iv[m], phi+iv[m]], value 0.5*cos(x[m]-phi)+0.5.
// Per row: y = C0 cos x0 + S0 sin x0 + C1 cos x1 + S1 sin x1 + C2 cos x2 + S2 sin x2 + T
// with coefficients a function of the rank triple (r0,r1,r2) of x[m] among
// each m's 32 sorted window bounds.
//   (C0,S0,T_total) = f(r0,r1,r2) -> 33^3 L2 table, 16B = 1 sector, 1 LDG.128
//   (C1,S1,C2,S2)   = f(r1,r2)    -> 1089-entry smem table, 1 conflict-lite LDS.128
// Rank: 3 register-pivot binary-search levels + 1 conflict-free LDS.128 + 4 cmp.
// Output: [ y (batch floats), weight (48 floats) ].

#define TPB 256
#define RPT 4
#define NR    33
#define NPAIR (NR * NR)       // 1089
#define NTAB  (NR * NR * NR)  // 35937

__device__ float  gSortedB[96];     // [m*32 + pos]
__device__ float4 gTrip[NTAB];      // (C0, S0, T_total, 0)
__device__ float4 gPairQ[NPAIR];    // (C1, S1, C2, S2)

// ---------------- fused setup ----------------------------------------------
__global__ void __launch_bounds__(TPB)
setup_all(const float* __restrict__ phis,
          const float* __restrict__ interval,
          const float* __restrict__ weight) {
    __shared__ float    sv[96];
    __shared__ int      spos[96];
    __shared__ float    svc[3][3][16];   // [m][{c,s,t}][l]
    __shared__ unsigned sSH[3][NR];

    const int t = threadIdx.x;

    if (t < 96) {
        const int m = t >> 5, i = t & 31, l = i & 15;
        const float p  = phis[m * 16 + l];
        const float iv = interval[m];
        sv[t] = (i < 16) ? (p - iv) : (p + iv);
    }
    if (t < 48) {
        const int m = t >> 4, l = t & 15;
        const float w = 0.5f * weight[3 * m + l];    // segment s = 3m + l
        const float p = phis[m * 16 + l];
        float sp, cp;
        sincosf(p, &sp, &cp);
        svc[m][0][l] = w * cp;
        svc[m][1][l] = w * sp;
        svc[m][2][l] = w;
    }
    __syncthreads();

    // stable rank-sort of each m's 32 bounds
    if (t < 96) {
        const int m = t >> 5, i = t & 31;
        const float v = sv[t];
        int pos = 0;
        for (int j = 0; j < 32; ++j) {
            const float u = sv[(m << 5) + j];
            pos += (u < v || (u == v && j < i)) ? 1 : 0;
        }
        spos[t] = pos;
        if (blockIdx.x == 0) gSortedB[(m << 5) + pos] = v;
    }
    __syncthreads();

    // hitmask per rank r in segment space: cond_l <=> pos(lo)<r && pos(hi)>=r
    if (t < 3 * NR) {
        const int m = t / NR, r = t - m * NR;
        unsigned mask = 0;
        for (int l = 0; l < 16; ++l) {
            const int plo  = spos[(m << 5) + l];
            const int phi_ = spos[(m << 5) + 16 + l];
            if (plo < r && phi_ >= r) mask |= (1u << l);
        }
        sSH[m][r] = mask << (3 * m);
    }
    __syncthreads();

    if (blockIdx.x == 0) {
        // pair table: W1 = H1 & ~H2, W2 = H2 (trig parts only; T folded below)
        for (int e = t; e < NPAIR; e += TPB) {
            const int r1 = e / NR, r2 = e - r1 * NR;
            const unsigned h2 = sSH[2][r2];
            const unsigned W1 = sSH[1][r1] & ~h2;
            float C1 = 0.f, S1 = 0.f, C2 = 0.f, S2 = 0.f;
            for (int l = 0; l < 16; ++l) {
                if (W1 & (1u << (3 + l))) { C1 += svc[1][0][l]; S1 += svc[1][1][l]; }
                if (h2 & (1u << (6 + l))) { C2 += svc[2][0][l]; S2 += svc[2][1][l]; }
            }
            gPairQ[e] = make_float4(C1, S1, C2, S2);
        }
    }

    // triple table: W0 = H0 & ~H1 & ~H2; T_total = T0 + T1 + T2
    for (int e = blockIdx.x * TPB + t; e < NTAB; e += gridDim.x * TPB) {
        const int r0  = e / NPAIR;
        const int rem = e - r0 * NPAIR;
        const int r1  = rem / NR;
        const int r2  = rem - r1 * NR;
        const unsigned h1 = sSH[1][r1], h2 = sSH[2][r2];
        const unsigned W0 = sSH[0][r0] & ~h1 & ~h2;
        const unsigned W1 = h1 & ~h2;
        float C = 0.f, S = 0.f, T = 0.f;
        for (int l = 0; l < 16; ++l) {
            if (W0 & (1u << l))       { C += svc[0][0][l]; S += svc[0][1][l]; T += svc[0][2][l]; }
            if (W1 & (1u << (3 + l))) { T += svc[1][2][l]; }
            if (h2 & (1u << (6 + l))) { T += svc[2][2][l]; }
        }
        gTrip[e] = make_float4(C, S, T, 0.0f);
    }
}

// ---------------- main ------------------------------------------------------
// rank = #{bounds < x}: 3 register-pivot levels, then one aligned LDS.128.
// piv = {b3,b7,b11,b15,b19,b23,b27}
__device__ __forceinline__ int rank32p(const float* __restrict__ b,
                                       const float piv[7], float xv) {
    int r = 0;
    if (piv[3] < xv) r = 16;                           // b[15]
    const float p8 = (r ? piv[5] : piv[1]);            // b[r+7]
    if (p8 < xv) r += 8;
    const float p4 = (r & 16) ? ((r & 8) ? piv[6] : piv[4])
                              : ((r & 8) ? piv[2] : piv[0]);  // b[r+3]
    if (p4 < xv) r += 4;
    // r % 4 == 0; count in [r, r+4]
    const float4 q = *reinterpret_cast<const float4*>(b + r);  // aligned 16B
    r += (q.x < xv) + (q.y < xv) + (q.z < xv) + (q.w < xv);
    return r;
}

__global__ void __launch_bounds__(TPB)
glm_main(const float* __restrict__ x,
         const float* __restrict__ weight,
         float* __restrict__ out, int batch) {
    __shared__ float  sb[96];
    __shared__ float4 sPQ[NPAIR];

    const int t = threadIdx.x;
    if (t < 96) sb[t] = gSortedB[t];
    for (int i = t; i < NPAIR; i += TPB) sPQ[i] = gPairQ[i];
    if (blockIdx.x == 0 && t < 48) out[batch + t] = weight[t];  // weight tail
    __syncthreads();

    const int tid = blockIdx.x * TPB + t;
    const long long row0 = (long long)tid * RPT;
    if (row0 >= batch) return;

    const float4* xv = reinterpret_cast<const float4*>(x + row0 * 3);
    const float4 va = xv[0], vb = xv[1], vc = xv[2];
    const float X[RPT][3] = {
        {va.x, va.y, va.z}, {va.w, vb.x, vb.y},
        {vb.z, vb.w, vc.x}, {vc.y, vc.z, vc.w}
    };

    // register pivots per m: b[3],b[7],b[11],b[15],b[19],b[23],b[27]
    float pv0[7], pv1[7], pv2[7];
#pragma unroll
    for (int i = 0; i < 7; ++i) {
        pv0[i] = sb[4 * i + 3];
        pv1[i] = sb[32 + 4 * i + 3];
        pv2[i] = sb[64 + 4 * i + 3];
    }

    float Y[RPT];
#pragma unroll
    for (int r = 0; r < RPT; ++r) {
        const float x0 = X[r][0], x1 = X[r][1], x2 = X[r][2];
        const int ra = rank32p(sb,      pv0, x0);
        const int rb = rank32p(sb + 32, pv1, x1);
        const int rc = rank32p(sb + 64, pv2, x2);

        const float4 tv = __ldg(&gTrip[(ra * NR + rb) * NR + rc]);  // 1 sector
        const float4 pq = sPQ[rb * NR + rc];

        float s0, c0, s1, c1, s2, c2;
        __sincosf(x0, &s0, &c0);
        __sincosf(x1, &s1, &c1);
        __sincosf(x2, &s2, &c2);

        float y = tv.z;                       // T_total
        y = fmaf(c0, tv.x, y); y = fmaf(s0, tv.y, y);
        y = fmaf(c1, pq.x, y); y = fmaf(s1, pq.y, y);
        y = fmaf(c2, pq.z, y); y = fmaf(s2, pq.w, y);
        Y[r] = y;
    }

    reinterpret_cast<float4*>(out)[tid] = make_float4(Y[0], Y[1], Y[2], Y[3]);
}

extern "C" void kernel_launch(void* const* d_in, const int* in_sizes, int n_in,
                              void* d_out, int out_size) {
    const float* x        = (const float*)d_in[0];
    const float* phis     = (const float*)d_in[1];
    const float* interval = (const float*)d_in[2];
    const float* weight   = (const float*)d_in[3];
    float* out = (float*)d_out;

    const int batch = in_sizes[0] / 3;
    const int n_threads = (batch + RPT - 1) / RPT;
    const int n_blocks  = (n_threads + TPB - 1) / TPB;

    setup_all<<<(NTAB + TPB - 1) / TPB, TPB>>>(phis, interval, weight);
    glm_main<<<n_blocks, TPB>>>(x, weight, out, batch);
}